// round 9
// baseline (speedup 1.0000x reference)
#include <cuda_runtime.h>

#define BB 16
#define NN 577
#define HH 12
#define DD 64
#define TQ 32
#define XS 2304          // x row stride (floats)
#define OS 768           // out row stride (floats)
#define SDIM 608         // padded key dim (19*32)
#define PTS 36           // Pt row stride (floats), 16B-aligned float4 at n0 multiples of 4
#define KSS 65           // K tile row stride (floats) -> conflict-free strided key access
#define SCALEF 0.125f    // 64^-0.5

// shared memory offsets (in floats)
#define OFF_S    0
#define OFF_PT   (OFF_S + TQ*SDIM)           // 19456
#define OFF_KS   (OFF_PT + SDIM*PTS)         // 41344  (reused: K tile [128][65] / V tile [128][64])
#define OFF_QS   (OFF_KS + 128*KSS)          // 49664  (Q transposed [64][32])
#define OFF_BV   (OFF_QS + 64*TQ)            // 51712
#define OFF_BH   (OFF_BV + TQ*24)            // 52480
#define OFF_B0   (OFF_BH + TQ*24)            // 53248
#define OFF_RS   (OFF_B0 + TQ)               // 53280
#define OFF_CS   (OFF_RS + TQ*24)            // 54048
#define OFF_P0   (OFF_CS + TQ*24)            // 54816
#define OFF_INV  (OFF_P0 + TQ)               // 54848
#define SMEM_FLOATS (OFF_INV + TQ)           // 54880 floats = 219,520 B (< 227 KB opt-in limit)

// rel_k table scratch lives inside the (not-yet-used) Pt region
#define OFF_TKV  OFF_PT
#define OFF_TKH  (OFF_PT + 30*KSS)

__device__ __forceinline__ int clip14(int v) {
    v = v < -14 ? -14 : (v > 14 ? 14 : v);
    return v + 15;
}

__global__ __launch_bounds__(256, 1)
void attn_kernel(const float* __restrict__ x, const float* __restrict__ wts,
                 const float* __restrict__ tkv, const float* __restrict__ tkh,
                 const float* __restrict__ tvv, const float* __restrict__ tvh,
                 float* __restrict__ out)
{
    extern __shared__ float sm[];
    const int tid = threadIdx.x;
    const int qt = blockIdx.x, h = blockIdx.y, b = blockIdx.z;
    const int n0 = qt * TQ;

    // per-head mixture weight: w = w2 + [h<10]*w1 + [h<8]*w0
    float w = __ldg(&wts[2]);
    if (h < 10) w += __ldg(&wts[1]);
    if (h < 8)  w += __ldg(&wts[0]);

    // ---------------- Phase A1: Q tile -> Qs[d][n] (scaled), rel_k tables -> smem scratch
    for (int idx = tid; idx < TQ * 16; idx += 256) {
        int n = idx >> 4, d4 = idx & 15;
        int qn = n0 + n;
        float4 f = make_float4(0.f, 0.f, 0.f, 0.f);
        if (qn < NN)
            f = *(const float4*)&x[((size_t)(b * NN + qn)) * XS + h * DD + d4 * 4];
        float* qp = &sm[OFF_QS + (d4 * 4) * TQ + n];
        qp[0 * TQ] = f.x * w; qp[1 * TQ] = f.y * w; qp[2 * TQ] = f.z * w; qp[3 * TQ] = f.w * w;
    }
    for (int idx = tid; idx < 2 * 30 * 16; idx += 256) {
        int which = (idx >= 480) ? 1 : 0;
        int i2 = idx - which * 480;
        int t = i2 >> 4, d4 = i2 & 15;
        const float* src = which ? tkh : tkv;
        float4 f = *(const float4*)&src[t * 64 + d4 * 4];
        float* dst = &sm[(which ? OFF_TKH : OFF_TKV) + t * KSS + d4 * 4];
        dst[0] = f.x; dst[1] = f.y; dst[2] = f.z; dst[3] = f.w;
    }
    __syncthreads();

    // ---------------- Phase A2: per-row rel-k bias coefficients (bv[24], bh[24], b0)
    {
        const float* skv = &sm[OFF_TKV];
        const float* skh = &sm[OFF_TKH];
        for (int task = tid; task < TQ * 49; task += 256) {
            int n = task & 31;
            int jj = task >> 5;
            int qn = n0 + n;
            bool zero_idx = (qn == 0) || (qn >= NN);
            int gq = 0, cq = 0;
            if (!zero_idx) { gq = (qn - 1) / 24; cq = (qn - 1) % 24; }
            const float* qcol = &sm[OFF_QS + n];
            if (jj == 0) {
                float s = 0.f;
                #pragma unroll 8
                for (int d = 0; d < 64; d++) s += qcol[d * TQ] * (skv[d] + skh[d]);
                sm[OFF_B0 + n] = s;
            } else if (jj <= 24) {
                int g = jj - 1;
                int t = zero_idx ? 0 : clip14(g - gq);
                const float* tr = &skv[t * KSS];
                float s = 0.f;
                #pragma unroll 8
                for (int d = 0; d < 64; d++) s += qcol[d * TQ] * tr[d];
                sm[OFF_BV + n * 24 + g] = s;
            } else {
                int c = jj - 25;
                int t = zero_idx ? 0 : clip14(c - cq);
                const float* tr = &skh[t * KSS];
                float s = 0.f;
                #pragma unroll 8
                for (int d = 0; d < 64; d++) s += qcol[d * TQ] * tr[d];
                sm[OFF_BH + n * 24 + c] = s;
            }
        }
    }
    __syncthreads();

    // ---------------- Phase A3: initialize S with bias (pre-SCALE), -1e30 on padded keys
    for (int idx = tid; idx < TQ * SDIM; idx += 256) {
        int n = idx / SDIM, m = idx - n * SDIM;
        float v;
        if (m >= NN)      v = -1e30f;
        else if (m == 0)  v = sm[OFF_B0 + n];
        else              v = sm[OFF_BV + n * 24 + (m - 1) / 24] + sm[OFF_BH + n * 24 + (m - 1) % 24];
        sm[OFF_S + n * SDIM + m] = v;
    }

    // ---------------- Phase B: S += Q K^T (register-blocked 4x4, key tiles of 128)
    {
        const int rb = tid >> 5, kb = tid & 31;
        for (int t0 = 0; t0 < SDIM; t0 += 128) {
            const int NK = (SDIM - t0 < 128) ? (SDIM - t0) : 128;
            __syncthreads();
            for (int idx = tid; idx < NK * 16; idx += 256) {
                int mm = idx >> 4, d4 = idx & 15;
                int m = t0 + mm;
                float4 f = make_float4(0.f, 0.f, 0.f, 0.f);
                if (m < NN)
                    f = *(const float4*)&x[((size_t)(b * NN + m)) * XS + 768 + h * DD + d4 * 4];
                float* kp = &sm[OFF_KS + mm * KSS + d4 * 4];
                kp[0] = f.x * w; kp[1] = f.y * w; kp[2] = f.z * w; kp[3] = f.w * w;
            }
            __syncthreads();

            float a00=0,a01=0,a02=0,a03=0, a10=0,a11=0,a12=0,a13=0;
            float a20=0,a21=0,a22=0,a23=0, a30=0,a31=0,a32=0,a33=0;
            const float* qb  = &sm[OFF_QS + rb * 4];
            const float* k0p = &sm[OFF_KS + kb * KSS];
            #pragma unroll 8
            for (int d = 0; d < 64; d++) {
                float4 q4 = *(const float4*)&qb[d * TQ];
                float k0 = k0p[d];
                float k1 = k0p[32 * KSS + d];
                float k2 = k0p[64 * KSS + d];
                float k3 = k0p[96 * KSS + d];
                a00 += q4.x * k0; a01 += q4.x * k1; a02 += q4.x * k2; a03 += q4.x * k3;
                a10 += q4.y * k0; a11 += q4.y * k1; a12 += q4.y * k2; a13 += q4.y * k3;
                a20 += q4.z * k0; a21 += q4.z * k1; a22 += q4.z * k2; a23 += q4.z * k3;
                a30 += q4.w * k0; a31 += q4.w * k1; a32 += q4.w * k2; a33 += q4.w * k3;
            }
            float acc[4][4] = {{a00,a01,a02,a03},{a10,a11,a12,a13},
                               {a20,a21,a22,a23},{a30,a31,a32,a33}};
            #pragma unroll
            for (int j = 0; j < 4; j++) {
                int ml = kb + 32 * j;
                if (ml < NK) {
                    #pragma unroll
                    for (int i = 0; i < 4; i++)
                        sm[OFF_S + (rb * 4 + i) * SDIM + t0 + ml] += acc[i][j];
                }
            }
        }
    }
    __syncthreads();

    // ---------------- Phase C: softmax (unnormalized p -> Pt[m][n], 1/sum deferred)
    {
        const int wid = tid >> 5, lane = tid & 31;
        for (int rr = 0; rr < 4; rr++) {
            int n = wid * 4 + rr;
            const float* srow = &sm[OFF_S + n * SDIM];
            float mx = -1e30f;
            for (int m = lane; m < SDIM; m += 32) mx = fmaxf(mx, srow[m]);
            #pragma unroll
            for (int o = 16; o; o >>= 1) mx = fmaxf(mx, __shfl_xor_sync(0xffffffffu, mx, o));
            float sum = 0.f;
            for (int m = lane; m < SDIM; m += 32) {
                float p = __expf((srow[m] - mx) * SCALEF);
                sm[OFF_PT + m * PTS + n] = p;
                sum += p;
            }
            #pragma unroll
            for (int o = 16; o; o >>= 1) sum += __shfl_xor_sync(0xffffffffu, sum, o);
            if (lane == 0) sm[OFF_INV + n] = 1.f / sum;
        }
    }
    __syncthreads();

    // ---------------- Phase D: 24-block row/col sums of p (rel-v binning), p0
    {
        const int wid = tid >> 5, lane = tid & 31;
        for (int rr = 0; rr < 4; rr++) {
            int n = wid * 4 + rr;
            if (lane < 24) {
                float rsv = 0.f, csv = 0.f;
                #pragma unroll 4
                for (int c = 0; c < 24; c++) rsv += sm[OFF_PT + (1 + 24 * lane + c) * PTS + n];
                #pragma unroll 4
                for (int g = 0; g < 24; g++) csv += sm[OFF_PT + (1 + 24 * g + lane) * PTS + n];
                sm[OFF_RS + n * 24 + lane] = rsv;
                sm[OFF_CS + n * 24 + lane] = csv;
            } else if (lane == 24) {
                sm[OFF_P0 + n] = sm[OFF_PT + n];   // p at m=0
            }
        }
    }

    // ---------------- Phase E: O = P V (two 128-thread groups split the m-range)
    {
        const int grp = tid >> 7, gt = tid & 127;
        const int rbp = gt >> 4, cb = gt & 15;
        float o00=0,o01=0,o02=0,o03=0, o10=0,o11=0,o12=0,o13=0;
        float o20=0,o21=0,o22=0,o23=0, o30=0,o31=0,o32=0,o33=0;
        for (int t0 = 0; t0 < SDIM; t0 += 128) {
            const int NK = (SDIM - t0 < 128) ? (SDIM - t0) : 128;
            __syncthreads();   // also fences Phase-D smem writes on iteration 0
            for (int idx = tid; idx < NK * 16; idx += 256) {
                int mm = idx >> 4, d4 = idx & 15;
                int m = t0 + mm;
                float4 f = make_float4(0.f, 0.f, 0.f, 0.f);
                if (m < NN)
                    f = *(const float4*)&x[((size_t)(b * NN + m)) * XS + 1536 + h * DD + d4 * 4];
                *(float4*)&sm[OFF_KS + mm * 64 + d4 * 4] =
                    make_float4(f.x * w, f.y * w, f.z * w, f.w * w);
            }
            __syncthreads();
            int mb = grp * 64;
            int cnt = NK - mb;
            if (cnt > 64) cnt = 64;
            if (cnt < 0)  cnt = 0;
            const float* ptb = &sm[OFF_PT + (t0 + mb) * PTS + rbp * 4];
            const float* vb  = &sm[OFF_KS + mb * 64 + cb * 4];
            #pragma unroll 4
            for (int mi = 0; mi < cnt; mi++) {
                float4 p4 = *(const float4*)&ptb[mi * PTS];
                float4 v4 = *(const float4*)&vb[mi * 64];
                o00 += p4.x * v4.x; o01 += p4.x * v4.y; o02 += p4.x * v4.z; o03 += p4.x * v4.w;
                o10 += p4.y * v4.x; o11 += p4.y * v4.y; o12 += p4.y * v4.z; o13 += p4.y * v4.w;
                o20 += p4.z * v4.x; o21 += p4.z * v4.y; o22 += p4.z * v4.z; o23 += p4.z * v4.w;
                o30 += p4.w * v4.x; o31 += p4.w * v4.y; o32 += p4.w * v4.z; o33 += p4.w * v4.w;
            }
        }
        __syncthreads();   // all tile compute done before S region is reused for partials
        float obuf[4][4] = {{o00,o01,o02,o03},{o10,o11,o12,o13},
                            {o20,o21,o22,o23},{o30,o31,o32,o33}};
        #pragma unroll
        for (int i = 0; i < 4; i++)
            *(float4*)&sm[OFF_S + grp * TQ * 64 + (rbp * 4 + i) * 64 + cb * 4] =
                make_float4(obuf[i][0], obuf[i][1], obuf[i][2], obuf[i][3]);
    }
    __syncthreads();

    // ---------------- Epilogue: reduce groups, add rel-v (49 rank-1 terms), normalize, store
    {
        int n  = tid >> 3;
        int d0 = (tid & 7) * 8;
        float o[8];
        #pragma unroll
        for (int dd = 0; dd < 8; dd++)
            o[dd] = sm[OFF_S + n * 64 + d0 + dd] + sm[OFF_S + TQ * 64 + n * 64 + d0 + dd];

        int qn = n0 + n;
        bool zero_idx = (qn == 0) || (qn >= NN);
        int gq = 0, cq = 0;
        if (!zero_idx) { gq = (qn - 1) / 24; cq = (qn - 1) % 24; }

        // m=0 term: p0 * (Tv[0] + Th[0])
        {
            float c0 = sm[OFF_P0 + n];
            float4 a  = __ldg((const float4*)&tvv[d0]);
            float4 a2 = __ldg((const float4*)&tvv[d0 + 4]);
            float4 bb = __ldg((const float4*)&tvh[d0]);
            float4 b2 = __ldg((const float4*)&tvh[d0 + 4]);
            o[0] += c0 * (a.x + bb.x); o[1] += c0 * (a.y + bb.y);
            o[2] += c0 * (a.z + bb.z); o[3] += c0 * (a.w + bb.w);
            o[4] += c0 * (a2.x + b2.x); o[5] += c0 * (a2.y + b2.y);
            o[6] += c0 * (a2.z + b2.z); o[7] += c0 * (a2.w + b2.w);
        }
        #pragma unroll 4
        for (int g = 0; g < 24; g++) {
            int t = zero_idx ? 0 : clip14(g - gq);
            float coef = sm[OFF_RS + n * 24 + g];
            const float* tr = &tvv[t * 64 + d0];
            float4 a  = __ldg((const float4*)tr);
            float4 a2 = __ldg((const float4*)(tr + 4));
            o[0] += coef * a.x;  o[1] += coef * a.y;  o[2] += coef * a.z;  o[3] += coef * a.w;
            o[4] += coef * a2.x; o[5] += coef * a2.y; o[6] += coef * a2.z; o[7] += coef * a2.w;
        }
        #pragma unroll 4
        for (int c = 0; c < 24; c++) {
            int t = zero_idx ? 0 : clip14(c - cq);
            float coef = sm[OFF_CS + n * 24 + c];
            const float* tr = &tvh[t * 64 + d0];
            float4 a  = __ldg((const float4*)tr);
            float4 a2 = __ldg((const float4*)(tr + 4));
            o[0] += coef * a.x;  o[1] += coef * a.y;  o[2] += coef * a.z;  o[3] += coef * a.w;
            o[4] += coef * a2.x; o[5] += coef * a2.y; o[6] += coef * a2.z; o[7] += coef * a2.w;
        }

        float invs = sm[OFF_INV + n];
        if (qn < NN) {
            float* op = &out[((size_t)(b * NN + qn)) * OS + h * DD + d0];
            *(float4*)op       = make_float4(o[0] * invs, o[1] * invs, o[2] * invs, o[3] * invs);
            *(float4*)(op + 4) = make_float4(o[4] * invs, o[5] * invs, o[6] * invs, o[7] * invs);
        }
    }
}

extern "C" void kernel_launch(void* const* d_in, const int* in_sizes, int n_in,
                              void* d_out, int out_size) {
    const float* x   = (const float*)d_in[0];
    const float* wts = (const float*)d_in[1];
    const float* tkv = (const float*)d_in[2];
    const float* tkh = (const float*)d_in[3];
    const float* tvv = (const float*)d_in[4];
    const float* tvh = (const float*)d_in[5];
    float* out = (float*)d_out;

    size_t smem = SMEM_FLOATS * sizeof(float);   // 219,520 B
    cudaFuncSetAttribute(attn_kernel, cudaFuncAttributeMaxDynamicSharedMemorySize, (int)smem);
    dim3 grid((NN + TQ - 1) / TQ, HH, BB);       // (19, 12, 16)
    attn_kernel<<<grid, 256, smem>>>(x, wts, tkv, tkh, tvv, tvh, out);
    (void)in_sizes; (void)n_in; (void)out_size;
}

// round 12
// speedup vs baseline: 1.7953x; 1.7953x over previous
#include <cuda_runtime.h>

#define BB 16
#define NN 577
#define HH 12
#define TQ 64
#define NT 512
#define XS 2304          // x row stride (floats)
#define OS 768           // out row stride (floats)
#define SDIM 608         // padded key dim (19*32)
#define SS 612           // S row stride (float4-aligned, bank-skewed by 4)
#define KSS 68           // K/V tile row stride -> conflict-free LDS.128 at lane stride
#define QSS 68
#define TKS 68
#define SCALEF 0.125f    // 64^-0.5

// shared memory offsets (in floats)
#define OFF_S    0                    // 64*612 = 39168 (scores -> p in place)
#define OFF_KS   (64*SS)              // 39168, 128*68 = 8704 (K tile / V tile / TK scratch / PV partials)
#define OFF_QS   (OFF_KS + 128*KSS)   // 47872, 64*68 = 4352 (Q row-major, scaled)
#define OFF_BV   (OFF_QS + 64*QSS)    // 52224, 64*24 (reused as RS)
#define OFF_BH   (OFF_BV + 64*24)     // 53760, 64*24 (reused as CS)
#define OFF_B0   (OFF_BH + 64*24)     // 55296, 64
#define OFF_P0   (OFF_B0 + 64)        // 55360, 64
#define OFF_INV  (OFF_P0 + 64)        // 55424, 64
#define SMEM_FLOATS (OFF_INV + 64)    // 55488 floats = 221,952 B

#define OFF_TKV  OFF_KS               // 30*68 = 2040
#define OFF_TKH  (OFF_KS + 30*TKS)    // 2040 more; ends 43248 < OFF_QS
#define OFF_PART OFF_KS               // PV partials: 2*4096 = 8192 <= 8704
#define OFF_RS   OFF_BV
#define OFF_CS   OFF_BH

__device__ __forceinline__ int clip14(int v) {
    v = v < -14 ? -14 : (v > 14 ? 14 : v);
    return v + 15;
}

#define DOT4(A, Q, K) { A += Q.x*K.x; A += Q.y*K.y; A += Q.z*K.z; A += Q.w*K.w; }

__global__ __launch_bounds__(NT, 1)
void attn_kernel(const float* __restrict__ x, const float* __restrict__ wts,
                 const float* __restrict__ tkv, const float* __restrict__ tkh,
                 const float* __restrict__ tvv, const float* __restrict__ tvh,
                 float* __restrict__ out)
{
    extern __shared__ float sm[];
    const int tid = threadIdx.x;
    const int qt = blockIdx.x, h = blockIdx.y, b = blockIdx.z;
    const int n0 = qt * TQ;

    // per-head mixture weight: w = w2 + [h<10]*w1 + [h<8]*w0
    float w = __ldg(&wts[2]);
    if (h < 10) w += __ldg(&wts[1]);
    if (h < 8)  w += __ldg(&wts[0]);

    // ---------------- Phase A1: Q tile -> QS[n][d] (scaled, natural layout); rel_k tables -> scratch
    for (int idx = tid; idx < TQ * 16; idx += NT) {
        int n = idx >> 4, d4 = idx & 15;
        int qn = n0 + n;
        float4 f = make_float4(0.f, 0.f, 0.f, 0.f);
        if (qn < NN)
            f = *(const float4*)&x[((size_t)(b * NN + qn)) * XS + h * 64 + d4 * 4];
        *(float4*)&sm[OFF_QS + n * QSS + d4 * 4] =
            make_float4(f.x * w, f.y * w, f.z * w, f.w * w);
    }
    for (int idx = tid; idx < 960; idx += NT) {
        int which = (idx >= 480) ? 1 : 0;
        int i2 = idx - which * 480;
        int t = i2 >> 4, d4 = i2 & 15;
        const float* src = which ? tkh : tkv;
        float4 f = *(const float4*)&src[t * 64 + d4 * 4];
        *(float4*)&sm[(which ? OFF_TKH : OFF_TKV) + t * TKS + d4 * 4] = f;
    }
    __syncthreads();

    // ---------------- Phase A2: per-row rel-k bias coefficients (b0, bv[24], bh[24])
    {
        int n = tid >> 3, l = tid & 7;
        int qn = n0 + n;
        bool zi = (qn == 0) || (qn >= NN);
        int gq = 0, cq = 0;
        if (!zi) { gq = (qn - 1) / 24; cq = (qn - 1) % 24; }
        const float4* qrow = (const float4*)&sm[OFF_QS + n * QSS];
        for (int jj = l; jj < 49; jj += 8) {
            float s = 0.f;
            if (jj == 0) {
                const float4* t0p = (const float4*)&sm[OFF_TKV];
                const float4* t1p = (const float4*)&sm[OFF_TKH];
                #pragma unroll 4
                for (int d4 = 0; d4 < 16; d4++) {
                    float4 q = qrow[d4];
                    float4 a = t0p[d4], c = t1p[d4];
                    s += q.x*(a.x+c.x) + q.y*(a.y+c.y) + q.z*(a.z+c.z) + q.w*(a.w+c.w);
                }
                sm[OFF_B0 + n] = s;
            } else if (jj <= 24) {
                int g = jj - 1;
                int t = zi ? 0 : clip14(g - gq);
                const float4* tr = (const float4*)&sm[OFF_TKV + t * TKS];
                #pragma unroll 4
                for (int d4 = 0; d4 < 16; d4++) { float4 q = qrow[d4], a = tr[d4]; DOT4(s, q, a); }
                sm[OFF_BV + n * 24 + g] = s;
            } else {
                int c = jj - 25;
                int t = zi ? 0 : clip14(c - cq);
                const float4* tr = (const float4*)&sm[OFF_TKH + t * TKS];
                #pragma unroll 4
                for (int d4 = 0; d4 < 16; d4++) { float4 q = qrow[d4], a = tr[d4]; DOT4(s, q, a); }
                sm[OFF_BH + n * 24 + c] = s;
            }
        }
    }

    // ---------------- Phase B: S = bias + Q K^T (4x4 register blocks, key tiles of 128, d-by-4 LDS.128)
    {
        const int rb = tid >> 5, kb = tid & 31;
        for (int t0 = 0; t0 < SDIM; t0 += 128) {
            const int NKS = (SDIM - t0 < 128) ? (SDIM - t0) : 128;
            __syncthreads();   // (first iter: fences A2's TK reads before KS overwrite)
            for (int idx = tid; idx < NKS * 16; idx += NT) {
                int mm = idx >> 4, d4 = idx & 15;
                int m = t0 + mm;
                float4 f = make_float4(0.f, 0.f, 0.f, 0.f);
                if (m < NN)
                    f = *(const float4*)&x[((size_t)(b * NN + m)) * XS + 768 + h * 64 + d4 * 4];
                *(float4*)&sm[OFF_KS + mm * KSS + d4 * 4] =
                    make_float4(f.x * w, f.y * w, f.z * w, f.w * w);
            }
            __syncthreads();

            float a_[4][4] = {{0,0,0,0},{0,0,0,0},{0,0,0,0},{0,0,0,0}};
            const float* qp = &sm[OFF_QS + (rb * 4) * QSS];
            const float* kp = &sm[OFF_KS + kb * KSS];
            #pragma unroll 4
            for (int d = 0; d < 64; d += 4) {
                float4 q0 = *(const float4*)&qp[0 * QSS + d];
                float4 q1 = *(const float4*)&qp[1 * QSS + d];
                float4 q2 = *(const float4*)&qp[2 * QSS + d];
                float4 q3 = *(const float4*)&qp[3 * QSS + d];
                float4 k0 = *(const float4*)&kp[0 * KSS + d];
                float4 k1 = *(const float4*)&kp[32 * KSS + d];
                float4 k2 = *(const float4*)&kp[64 * KSS + d];
                float4 k3 = *(const float4*)&kp[96 * KSS + d];
                DOT4(a_[0][0], q0, k0); DOT4(a_[0][1], q0, k1); DOT4(a_[0][2], q0, k2); DOT4(a_[0][3], q0, k3);
                DOT4(a_[1][0], q1, k0); DOT4(a_[1][1], q1, k1); DOT4(a_[1][2], q1, k2); DOT4(a_[1][3], q1, k3);
                DOT4(a_[2][0], q2, k0); DOT4(a_[2][1], q2, k1); DOT4(a_[2][2], q2, k2); DOT4(a_[2][3], q2, k3);
                DOT4(a_[3][0], q3, k0); DOT4(a_[3][1], q3, k1); DOT4(a_[3][2], q3, k2); DOT4(a_[3][3], q3, k3);
            }
            // writeback with fused bias init (zero-filled K rows give acc=0 for m>=NN)
            #pragma unroll
            for (int j = 0; j < 4; j++) {
                int ml = kb + 32 * j;
                if (ml < NKS) {
                    int m = t0 + ml;
                    int gm = (m - 1) / 24, cm = (m - 1) % 24;
                    #pragma unroll
                    for (int i = 0; i < 4; i++) {
                        int r = rb * 4 + i;
                        float bias;
                        if (m >= NN)      bias = -1e30f;
                        else if (m == 0)  bias = sm[OFF_B0 + r];
                        else              bias = sm[OFF_BV + r * 24 + gm] + sm[OFF_BH + r * 24 + cm];
                        sm[OFF_S + r * SS + m] = bias + a_[i][j];
                    }
                }
            }
        }
    }
    __syncthreads();

    // ---------------- Phase C: softmax in place (p unnormalized; 1/sum deferred)
    {
        const int wid = tid >> 5, lane = tid & 31;
        for (int rr = 0; rr < 4; rr++) {
            int n = wid * 4 + rr;
            float* srow = &sm[OFF_S + n * SS];
            float mx = -1e30f;
            for (int m = lane; m < SDIM; m += 32) mx = fmaxf(mx, srow[m]);
            #pragma unroll
            for (int o = 16; o; o >>= 1) mx = fmaxf(mx, __shfl_xor_sync(0xffffffffu, mx, o));
            float sum = 0.f;
            for (int m = lane; m < SDIM; m += 32) {
                float p = __expf((srow[m] - mx) * SCALEF);
                srow[m] = p;
                sum += p;
            }
            #pragma unroll
            for (int o = 16; o; o >>= 1) sum += __shfl_xor_sync(0xffffffffu, sum, o);
            if (lane == 0) sm[OFF_INV + n] = 1.f / sum;
        }
    }
    __syncthreads();

    // ---------------- Phase D: 24-block row/col sums of p (rel-v binning), p0
    {
        const int wid = tid >> 5, lane = tid & 31;
        for (int rr = 0; rr < 4; rr++) {
            int n = wid * 4 + rr;
            const float* pr = &sm[OFF_S + n * SS];
            if (lane < 24) {
                float rsv = 0.f, csv = 0.f;
                #pragma unroll 4
                for (int k = 0; k < 24; k++) {
                    rsv += pr[1 + 24 * lane + k];
                    csv += pr[1 + 24 * k + lane];
                }
                sm[OFF_RS + n * 24 + lane] = rsv;
                sm[OFF_CS + n * 24 + lane] = csv;
            } else if (lane == 24) {
                sm[OFF_P0 + n] = pr[0];
            }
        }
    }

    // ---------------- Phase E: O = P V (two 256-thread groups split each 128-row V tile)
    {
        const int grp = tid >> 8, gt = tid & 255;
        const int rbp = gt >> 4, cb = gt & 15;
        float a_[4][4] = {{0,0,0,0},{0,0,0,0},{0,0,0,0},{0,0,0,0}};
        for (int t0 = 0; t0 < NN; t0 += 128) {
            const int NKS = (SDIM - t0 < 128) ? (SDIM - t0) : 128;
            __syncthreads();   // (first iter: fences Phase-D reads of S / orders KS reuse)
            for (int idx = tid; idx < NKS * 16; idx += NT) {
                int mm = idx >> 4, d4 = idx & 15;
                int m = t0 + mm;
                float4 f = make_float4(0.f, 0.f, 0.f, 0.f);
                if (m < NN)
                    f = *(const float4*)&x[((size_t)(b * NN + m)) * XS + 1536 + h * 64 + d4 * 4];
                *(float4*)&sm[OFF_KS + mm * KSS + d4 * 4] =
                    make_float4(f.x * w, f.y * w, f.z * w, f.w * w);
            }
            __syncthreads();
            int mstart = grp * 64;
            int cnt = NN - t0 - mstart;
            if (cnt > 64) cnt = 64;
            if (cnt < 0)  cnt = 0;
            int cnt4 = (cnt + 3) & ~3;     // over-read hits zero-filled V rows & p==0 cols
            const float* pp = &sm[OFF_S + (rbp * 4) * SS + t0 + mstart];
            const float* vp = &sm[OFF_KS + mstart * KSS + cb * 4];
            #pragma unroll 2
            for (int mi = 0; mi < cnt4; mi += 4) {
                float4 p0 = *(const float4*)&pp[0 * SS + mi];
                float4 p1 = *(const float4*)&pp[1 * SS + mi];
                float4 p2 = *(const float4*)&pp[2 * SS + mi];
                float4 p3 = *(const float4*)&pp[3 * SS + mi];
                float4 v0 = *(const float4*)&vp[(mi + 0) * KSS];
                float4 v1 = *(const float4*)&vp[(mi + 1) * KSS];
                float4 v2 = *(const float4*)&vp[(mi + 2) * KSS];
                float4 v3 = *(const float4*)&vp[(mi + 3) * KSS];
                a_[0][0] += p0.x*v0.x; a_[0][0] += p0.y*v1.x; a_[0][0] += p0.z*v2.x; a_[0][0] += p0.w*v3.x;
                a_[0][1] += p0.x*v0.y; a_[0][1] += p0.y*v1.y; a_[0][1] += p0.z*v2.y; a_[0][1] += p0.w*v3.y;
                a_[0][2] += p0.x*v0.z; a_[0][2] += p0.y*v1.z; a_[0][2] += p0.z*v2.z; a_[0][2] += p0.w*v3.z;
                a_[0][3] += p0.x*v0.w; a_[0][3] += p0.y*v1.w; a_[0][3] += p0.z*v2.w; a_[0][3] += p0.w*v3.w;
                a_[1][0] += p1.x*v0.x; a_[1][0] += p1.y*v1.x; a_[1][0] += p1.z*v2.x; a_[1][0] += p1.w*v3.x;
                a_[1][1] += p1.x*v0.y; a_[1][1] += p1.y*v1.y; a_[1][1] += p1.z*v2.y; a_[1][1] += p1.w*v3.y;
                a_[1][2] += p1.x*v0.z; a_[1][2] += p1.y*v1.z; a_[1][2] += p1.z*v2.z; a_[1][2] += p1.w*v3.z;
                a_[1][3] += p1.x*v0.w; a_[1][3] += p1.y*v1.w; a_[1][3] += p1.z*v2.w; a_[1][3] += p1.w*v3.w;
                a_[2][0] += p2.x*v0.x; a_[2][0] += p2.y*v1.x; a_[2][0] += p2.z*v2.x; a_[2][0] += p2.w*v3.x;
                a_[2][1] += p2.x*v0.y; a_[2][1] += p2.y*v1.y; a_[2][1] += p2.z*v2.y; a_[2][1] += p2.w*v3.y;
                a_[2][2] += p2.x*v0.z; a_[2][2] += p2.y*v1.z; a_[2][2] += p2.z*v2.z; a_[2][2] += p2.w*v3.z;
                a_[2][3] += p2.x*v0.w; a_[2][3] += p2.y*v1.w; a_[2][3] += p2.z*v2.w; a_[2][3] += p2.w*v3.w;
                a_[3][0] += p3.x*v0.x; a_[3][0] += p3.y*v1.x; a_[3][0] += p3.z*v2.x; a_[3][0] += p3.w*v3.x;
                a_[3][1] += p3.x*v0.y; a_[3][1] += p3.y*v1.y; a_[3][1] += p3.z*v2.y; a_[3][1] += p3.w*v3.y;
                a_[3][2] += p3.x*v0.z; a_[3][2] += p3.y*v1.z; a_[3][2] += p3.z*v2.z; a_[3][2] += p3.w*v3.z;
                a_[3][3] += p3.x*v0.w; a_[3][3] += p3.y*v1.w; a_[3][3] += p3.z*v2.w; a_[3][3] += p3.w*v3.w;
            }
        }
        __syncthreads();   // tile compute done before KS is reused for partials
        #pragma unroll
        for (int i = 0; i < 4; i++)
            *(float4*)&sm[OFF_PART + grp * 4096 + (rbp * 4 + i) * 64 + cb * 4] =
                make_float4(a_[i][0], a_[i][1], a_[i][2], a_[i][3]);
    }
    __syncthreads();

    // ---------------- Epilogue: reduce groups, add rel-v (49 rank-1 terms), normalize, store
    {
        int n  = tid >> 3;
        int d0 = (tid & 7) * 8;
        float o[8];
        #pragma unroll
        for (int dd = 0; dd < 8; dd++)
            o[dd] = sm[OFF_PART + n * 64 + d0 + dd] + sm[OFF_PART + 4096 + n * 64 + d0 + dd];

        int qn = n0 + n;
        bool zi = (qn == 0) || (qn >= NN);
        int gq = 0, cq = 0;
        if (!zi) { gq = (qn - 1) / 24; cq = (qn - 1) % 24; }

        // m=0 term: p0 * (Tv[0] + Th[0])
        {
            float c0 = sm[OFF_P0 + n];
            float4 a  = __ldg((const float4*)&tvv[d0]);
            float4 a2 = __ldg((const float4*)&tvv[d0 + 4]);
            float4 bb = __ldg((const float4*)&tvh[d0]);
            float4 b2 = __ldg((const float4*)&tvh[d0 + 4]);
            o[0] += c0 * (a.x + bb.x); o[1] += c0 * (a.y + bb.y);
            o[2] += c0 * (a.z + bb.z); o[3] += c0 * (a.w + bb.w);
            o[4] += c0 * (a2.x + b2.x); o[5] += c0 * (a2.y + b2.y);
            o[6] += c0 * (a2.z + b2.z); o[7] += c0 * (a2.w + b2.w);
        }
        #pragma unroll 4
        for (int g = 0; g < 24; g++) {
            int t = zi ? 0 : clip14(g - gq);
            float coef = sm[OFF_RS + n * 24 + g];
            const float* tr = &tvv[t * 64 + d0];
            float4 a  = __ldg((const float4*)tr);
            float4 a2 = __ldg((const float4*)(tr + 4));
            o[0] += coef * a.x;  o[1] += coef * a.y;  o[2] += coef * a.z;  o[3] += coef * a.w;
            o[4] += coef * a2.x; o[5] += coef * a2.y; o[6] += coef * a2.z; o[7] += coef * a2.w;
        }
        #pragma unroll 4
        for (int c = 0; c < 24; c++) {
            int t = zi ? 0 : clip14(c - cq);
            float coef = sm[OFF_CS + n * 24 + c];
            const float* tr = &tvh[t * 64 + d0];
            float4 a  = __ldg((const float4*)tr);
            float4 a2 = __ldg((const float4*)(tr + 4));
            o[0] += coef * a.x;  o[1] += coef * a.y;  o[2] += coef * a.z;  o[3] += coef * a.w;
            o[4] += coef * a2.x; o[5] += coef * a2.y; o[6] += coef * a2.z; o[7] += coef * a2.w;
        }

        float invs = sm[OFF_INV + n];
        if (qn < NN) {
            float* op = &out[((size_t)(b * NN + qn)) * OS + h * 64 + d0];
            *(float4*)op       = make_float4(o[0] * invs, o[1] * invs, o[2] * invs, o[3] * invs);
            *(float4*)(op + 4) = make_float4(o[4] * invs, o[5] * invs, o[6] * invs, o[7] * invs);
        }
    }
}

extern "C" void kernel_launch(void* const* d_in, const int* in_sizes, int n_in,
                              void* d_out, int out_size) {
    const float* x   = (const float*)d_in[0];
    const float* wts = (const float*)d_in[1];
    const float* tkv = (const float*)d_in[2];
    const float* tkh = (const float*)d_in[3];
    const float* tvv = (const float*)d_in[4];
    const float* tvh = (const float*)d_in[5];
    float* out = (float*)d_out;

    size_t smem = SMEM_FLOATS * sizeof(float);   // 221,952 B
    cudaFuncSetAttribute(attn_kernel, cudaFuncAttributeMaxDynamicSharedMemorySize, (int)smem);
    dim3 grid((NN + TQ - 1) / TQ, HH, BB);       // (10, 12, 16)
    attn_kernel<<<grid, NT, smem>>>(x, wts, tkv, tkh, tvv, tvh, out);
    (void)in_sizes; (void)n_in; (void)out_size;
}